// round 4
// baseline (speedup 1.0000x reference)
#include <cuda_runtime.h>
#include <cstddef>

// GraphSage gather + cosine top-16 + mean.  (Round 4)
//   d_in[0] nodes  : int32 [N]
//   d_in[1] neigh  : int32 [N, 32]
//   d_in[2] u2e_visual : f32 [500000, 64]
//   d_in[3] u2e_text   : f32 [500000, 64]
// Output: f32 concat(u_v, u_t, v_agg, t_agg), each [N, 64].
//
// One warp per (node, modality), modality-major order (single-table L2 phase).
// Sim loop: 8-lane groups, explicit 4-row load batches (8 LDG.128 in flight
// before any consume) to raise MLP_eff and cut long-scoreboard stalls.
// Ranking: strictly-monotone transform dot*|dot|/||v||^2 (no sqrt).
// Mean loop: 16-lane halves over the top-16 rows (L1-resident re-reads).
// Output/index streams use evict-first hints to protect L2 table residency.

#define DEG   32
#define TOPK  16
#define EMB   64

__global__ __launch_bounds__(256, 5) void gs_kernel(
    const int*   __restrict__ nodes,
    const int*   __restrict__ neigh,
    const float* __restrict__ uv,
    const float* __restrict__ ut,
    float*       __restrict__ out,
    int n)
{
    const unsigned FULL = 0xffffffffu;
    int wg = (int)((blockIdx.x * blockDim.x + threadIdx.x) >> 5);
    if (wg >= 2 * n) return;
    int lane = threadIdx.x & 31;

    // modality-major task order: [0,n) = visual, [n,2n) = text
    int m    = (wg >= n) ? 1 : 0;
    int node = wg - m * n;
    const float* __restrict__ emb = m ? ut : uv;

    int g = lane >> 3;     // 8-lane group id (0..3) — one neighbor per group
    int s = lane & 7;      // sub-lane within group — 8 floats per lane

    // ---- center gather (lane s holds float4 s and s+8 of the row) ----
    int cidx = __ldcs(nodes + node);
    const float4* crow = (const float4*)(emb + (size_t)cidx * EMB);
    float4 ua = __ldg(crow + s);
    float4 ub = __ldg(crow + s + 8);

    size_t nn = (size_t)n * EMB;
    float4* cout = (float4*)(out + (size_t)m * nn + (size_t)node * EMB);
    if (g == 0) { __stcs(cout + s, ua); __stcs(cout + s + 8, ub); }

    // ---- neighbor indices: lane k holds neigh[node][k] ----
    int nidx = __ldcs(neigh + (size_t)node * DEG + lane);

    // ---- ranking value: dot*|dot|/||v||^2 (monotone in cosine; center norm
    //      is a positive per-node constant, irrelevant to ordering) ----
    float tmp = 0.0f;
    #pragma unroll
    for (int h = 0; h < 2; h++) {                // two batches of 4 iterations
        int    jj[4];
        float4 va[4], vb[4];
        // 1) gather indices for this batch
        #pragma unroll
        for (int t = 0; t < 4; t++)
            jj[t] = __shfl_sync(FULL, nidx, 4 * (4 * h + t) + g);
        // 2) issue all 8 row-loads before consuming (MLP ~ 8)
        #pragma unroll
        for (int t = 0; t < 4; t++) {
            const float4* vrow = (const float4*)(emb + (size_t)jj[t] * EMB);
            va[t] = __ldg(vrow + s);
            vb[t] = __ldg(vrow + s + 8);
        }
        // 3) dot/nsq + 3-step butterfly per 8-lane group
        #pragma unroll
        for (int t = 0; t < 4; t++) {
            float dot = va[t].x * ua.x + va[t].y * ua.y + va[t].z * ua.z + va[t].w * ua.w
                      + vb[t].x * ub.x + vb[t].y * ub.y + vb[t].z * ub.z + vb[t].w * ub.w;
            float nsq = va[t].x * va[t].x + va[t].y * va[t].y + va[t].z * va[t].z + va[t].w * va[t].w
                      + vb[t].x * vb[t].x + vb[t].y * vb[t].y + vb[t].z * vb[t].z + vb[t].w * vb[t].w;
            #pragma unroll
            for (int d = 1; d < 8; d <<= 1) {
                dot += __shfl_xor_sync(FULL, dot, d);
                nsq += __shfl_xor_sync(FULL, nsq, d);
            }
            float r = __fdividef(dot * fabsf(dot), nsq + 1e-20f);
            if (s == 4 * h + t) tmp = r;         // lane L holds r(4*(L&7)+(L>>3))
        }
    }
    // redistribute so lane j holds r(j): src(j) = ((j&3)<<3) | (j>>2)
    float mysim = __shfl_sync(FULL, tmp, ((lane & 3) << 3) | (lane >> 2));

    // ---- stable top-16 via rank count (matches jax.lax.top_k tie-break) ----
    int cnt = 0;
    #pragma unroll
    for (int jl = 0; jl < DEG; jl++) {
        float o = __shfl_sync(FULL, mysim, jl);
        cnt += (o > mysim) || (o == mysim && jl < lane);
    }
    unsigned sel = __ballot_sync(FULL, cnt < TOPK);   // exactly TOPK bits set

    // ---- mean of selected (unnormalized) rows; re-reads hit L1 ----
    int half = lane >> 4;   // 16-lane halves: 2 neighbors per iteration
    int sub  = lane & 15;
    float4 acc = make_float4(0.f, 0.f, 0.f, 0.f);
    #pragma unroll
    for (int k = 0; k < DEG; k += 2) {
        int kk = k + half;
        int j = __shfl_sync(FULL, nidx, kk);
        if (sel & (1u << kk)) {
            float4 v = __ldg((const float4*)(emb + (size_t)j * EMB) + sub);
            acc.x += v.x; acc.y += v.y; acc.z += v.z; acc.w += v.w;
        }
    }
    acc.x += __shfl_xor_sync(FULL, acc.x, 16);
    acc.y += __shfl_xor_sync(FULL, acc.y, 16);
    acc.z += __shfl_xor_sync(FULL, acc.z, 16);
    acc.w += __shfl_xor_sync(FULL, acc.w, 16);

    if (half == 0) {
        const float sc = 1.0f / (float)TOPK;
        float4 r = make_float4(acc.x * sc, acc.y * sc, acc.z * sc, acc.w * sc);
        float4* aout = (float4*)(out + (size_t)(2 + m) * nn + (size_t)node * EMB);
        __stcs(aout + sub, r);
    }
}

extern "C" void kernel_launch(void* const* d_in, const int* in_sizes, int n_in,
                              void* d_out, int out_size) {
    const int*   nodes = (const int*)d_in[0];
    const int*   neigh = (const int*)d_in[1];
    const float* uv    = (const float*)d_in[2];
    const float* ut    = (const float*)d_in[3];
    float*       out   = (float*)d_out;
    int n = in_sizes[0];
    int warps = 2 * n;
    int threads = 256;
    int blocks = (warps * 32 + threads - 1) / threads;
    gs_kernel<<<blocks, threads>>>(nodes, neigh, uv, ut, out, n);
}